// round 15
// baseline (speedup 1.0000x reference)
#include <cuda_runtime.h>
#include <cuda_bf16.h>

// Fixed problem shapes
#define N_C 500000
#define N_F 2000000
#define KNBR 8
#define TPB 256

// Scratch: d = input - pred, padded to float4 (16B-aligned single-sector gathers).
__device__ float4 g_d[N_C + N_F];
__device__ double g_acc;
__device__ unsigned int g_done;

// ---------------------------------------------------------------------------
// diff for one 256-vertex tile (float4 loads + smem transpose).
// ---------------------------------------------------------------------------
__device__ __forceinline__ void diff_tile(const float* __restrict__ a,
                                          const float* __restrict__ p,
                                          int n, int segbase, int tile,
                                          float* s /* 3*TPB floats */) {
    const int t = threadIdx.x;
    const int v0 = tile * TPB;
    if (v0 + TPB <= n) {
        const int f4base = (v0 >> 2) * 3;      // exact: v0 % 4 == 0
        if (t < 3 * TPB / 4) {
            float4 av = __ldcs((const float4*)a + f4base + t);
            float4 pv = __ldcs((const float4*)p + f4base + t);
            ((float4*)s)[t] = make_float4(av.x - pv.x, av.y - pv.y,
                                          av.z - pv.z, av.w - pv.w);
        }
        __syncthreads();
        // stride-3 smem reads: gcd(3,32)=1 -> conflict-free
        g_d[segbase + v0 + t] =
            make_float4(s[3 * t], s[3 * t + 1], s[3 * t + 2], 0.0f);
    } else {
        const int i = v0 + t;
        if (i < n) {
            const int b3 = 3 * i;
            g_d[segbase + i] = make_float4(a[b3 + 0] - p[b3 + 0],
                                           a[b3 + 1] - p[b3 + 1],
                                           a[b3 + 2] - p[b3 + 2], 0.0f);
        }
    }
}

// ---------------------------------------------------------------------------
// Per-vertex loss term (R12-measured config: int2 rows + __ldcs).
// ---------------------------------------------------------------------------
__device__ __forceinline__ float loss_vertex(const int* __restrict__ lap,
                                             const float4* __restrict__ d,
                                             int i) {
    const float4 di = d[i];

    const int2* __restrict__ r2 = (const int2*)lap + (size_t)i * 5;
    const int2 p0 = __ldcs(r2 + 0);
    const int2 p1 = __ldcs(r2 + 1);
    const int2 p2 = __ldcs(r2 + 2);
    const int2 p3 = __ldcs(r2 + 3);
    const int2 p4 = __ldcs(r2 + 4);  // p4.y = count
    int idx[KNBR] = {p0.x, p0.y, p1.x, p1.y, p2.x, p2.y, p3.x, p3.y};

    float sx = 0.0f, sy = 0.0f, sz = 0.0f;
#pragma unroll
    for (int j = 0; j < KNBR; j++) {
        const int id = idx[j];
        if (id >= 0) {
            const float4 nv = d[id];
            sx += nv.x; sy += nv.y; sz += nv.z;
        }
    }
    const float inv = 1.0f / (float)p4.y;
    const float ex = di.x - sx * inv;
    const float ey = di.y - sy * inv;
    const float ez = di.z - sz * inv;
    return ex * ex + ey * ey + ez * ez;
}

// Block reduction -> scaled atomicAdd into g_acc; counts toward g_done.
__device__ __forceinline__ void block_add_count(float v, double scale) {
#pragma unroll
    for (int off = 16; off > 0; off >>= 1)
        v += __shfl_down_sync(0xFFFFFFFFu, v, off);

    __shared__ float warp_sums[TPB / 32];
    const int lane = threadIdx.x & 31;
    const int wid  = threadIdx.x >> 5;
    if (lane == 0) warp_sums[wid] = v;
    __syncthreads();

    if (wid == 0) {
        float s = (lane < (TPB >> 5)) ? warp_sums[lane] : 0.0f;
#pragma unroll
        for (int off = 4; off > 0; off >>= 1)
            s += __shfl_down_sync(0xFFFFFFFFu, s, off);
        if (lane == 0) {
            atomicAdd(&g_acc, (double)s * scale);
            __threadfence();
            atomicAdd(&g_done, 1u);
        }
    }
}

// ---------------------------------------------------------------------------
// K1: diff FINE (the critical-path producer) + reset state.
// ---------------------------------------------------------------------------
__global__ void diff_fine_kernel(const float* __restrict__ fi,
                                 const float* __restrict__ fp,
                                 int nc, int nf) {
    __shared__ float s[3 * TPB];
    if (blockIdx.x == 0 && threadIdx.x == 0) { g_acc = 0.0; g_done = 0u; }
    diff_tile(fi, fp, nf, nc, blockIdx.x, s);
}

// ---------------------------------------------------------------------------
// K2: mixed — blocks [0, flb) compute loss_fine (the 72us pole, scheduled
// first); blocks [flb, ..) do diff_coarse (DRAM work, hides under the pole).
// Independent: loss_fine reads only the fine region of g_d.
// __launch_bounds__(TPB, 8): cap 32 regs -> 64 warps/SM for the gather pole.
// ---------------------------------------------------------------------------
__global__ void __launch_bounds__(TPB, 8)
mixed_kernel(const int* __restrict__ lif,
             const float* __restrict__ ci,
             const float* __restrict__ cp,
             int nc, int nf, int flb, double sf) {
    const int b = blockIdx.x;
    if (b < flb) {
        const int i = b * TPB + threadIdx.x;
        float v = (i < nf) ? loss_vertex(lif, g_d + nc, i) : 0.0f;
        block_add_count(v, sf);
    } else {
        __shared__ float s[3 * TPB];
        diff_tile(ci, cp, nc, 0, b - flb, s);
    }
}

// ---------------------------------------------------------------------------
// K3: loss_coarse + last-block finalize (last launch -> finishing block here).
// ---------------------------------------------------------------------------
__global__ void __launch_bounds__(TPB, 8)
loss_coarse_kernel(const int* __restrict__ lic, int nc,
                   double sc, unsigned int total_blocks,
                   float* __restrict__ out) {
    const int i = blockIdx.x * TPB + threadIdx.x;
    float v = (i < nc) ? loss_vertex(lic, g_d, i) : 0.0f;

#pragma unroll
    for (int off = 16; off > 0; off >>= 1)
        v += __shfl_down_sync(0xFFFFFFFFu, v, off);

    __shared__ float warp_sums[TPB / 32];
    __shared__ bool is_last;
    const int lane = threadIdx.x & 31;
    const int wid  = threadIdx.x >> 5;
    if (lane == 0) warp_sums[wid] = v;
    __syncthreads();

    if (wid == 0) {
        float s = (lane < (TPB >> 5)) ? warp_sums[lane] : 0.0f;
#pragma unroll
        for (int off = 4; off > 0; off >>= 1)
            s += __shfl_down_sync(0xFFFFFFFFu, s, off);
        if (lane == 0) {
            atomicAdd(&g_acc, (double)s * sc);
            __threadfence();
            unsigned int old = atomicAdd(&g_done, 1u);
            is_last = (old == total_blocks - 1u);
        }
    }
    __syncthreads();

    if (is_last && threadIdx.x == 0) {
        __threadfence();
        out[0] = (float)g_acc;
    }
}

extern "C" void kernel_launch(void* const* d_in, const int* in_sizes, int n_in,
                              void* d_out, int out_size) {
    const float* ci = (const float*)d_in[0];  // coarse_input  (N_C,3)
    const float* cp = (const float*)d_in[1];  // coarse_pred   (N_C,3)
    const float* fi = (const float*)d_in[2];  // fine_input    (N_F,3)
    const float* fp = (const float*)d_in[3];  // fine_pred     (N_F,3)
    const int* lic  = (const int*)d_in[4];    // lap_idx_coarse (N_C,10)
    const int* lif  = (const int*)d_in[5];    // lap_idx_fine   (N_F,10)

    const int nc = in_sizes[0] / 3;
    const int nf = in_sizes[2] / 3;

    const int cb  = (nc + TPB - 1) / TPB;   // coarse tiles / loss blocks
    const int fb  = (nf + TPB - 1) / TPB;   // fine tiles / loss blocks
    const unsigned int total = (unsigned int)(cb + fb);  // loss blocks overall

    diff_fine_kernel<<<fb, TPB>>>(fi, fp, nc, nf);
    mixed_kernel<<<fb + cb, TPB>>>(lif, ci, cp, nc, nf, fb, 0.5 / (double)nf);
    loss_coarse_kernel<<<cb, TPB>>>(lic, nc, 0.5 / (double)nc, total,
                                    (float*)d_out);
}

// round 16
// speedup vs baseline: 1.0860x; 1.0860x over previous
#include <cuda_runtime.h>
#include <cuda_bf16.h>

// Fixed problem shapes
#define N_C 500000
#define N_F 2000000
#define KNBR 8
#define TPB 256

// Scratch: d = input - pred, padded to float4 (16B-aligned single-sector gathers).
__device__ float4 g_d[N_C + N_F];
__device__ double g_acc;
__device__ unsigned int g_done;

// ---------------------------------------------------------------------------
// diff for one 256-vertex tile (float4 loads + smem transpose).
// ---------------------------------------------------------------------------
__device__ __forceinline__ void diff_tile(const float* __restrict__ a,
                                          const float* __restrict__ p,
                                          int n, int segbase, int tile,
                                          float* s /* 3*TPB floats */) {
    const int t = threadIdx.x;
    const int v0 = tile * TPB;
    if (v0 + TPB <= n) {
        const int f4base = (v0 >> 2) * 3;      // exact: v0 % 4 == 0
        if (t < 3 * TPB / 4) {
            float4 av = __ldcs((const float4*)a + f4base + t);
            float4 pv = __ldcs((const float4*)p + f4base + t);
            ((float4*)s)[t] = make_float4(av.x - pv.x, av.y - pv.y,
                                          av.z - pv.z, av.w - pv.w);
        }
        __syncthreads();
        // stride-3 smem reads: gcd(3,32)=1 -> conflict-free
        g_d[segbase + v0 + t] =
            make_float4(s[3 * t], s[3 * t + 1], s[3 * t + 2], 0.0f);
    } else {
        const int i = v0 + t;
        if (i < n) {
            const int b3 = 3 * i;
            g_d[segbase + i] = make_float4(a[b3 + 0] - p[b3 + 0],
                                           a[b3 + 1] - p[b3 + 1],
                                           a[b3 + 2] - p[b3 + 2], 0.0f);
        }
    }
}

// ---------------------------------------------------------------------------
// Per-vertex loss term (R12-measured config: int2 rows + __ldcs, 36 regs).
// ---------------------------------------------------------------------------
__device__ __forceinline__ float loss_vertex(const int* __restrict__ lap,
                                             const float4* __restrict__ d,
                                             int i) {
    const float4 di = d[i];

    const int2* __restrict__ r2 = (const int2*)lap + (size_t)i * 5;
    const int2 p0 = __ldcs(r2 + 0);
    const int2 p1 = __ldcs(r2 + 1);
    const int2 p2 = __ldcs(r2 + 2);
    const int2 p3 = __ldcs(r2 + 3);
    const int2 p4 = __ldcs(r2 + 4);  // p4.y = count
    int idx[KNBR] = {p0.x, p0.y, p1.x, p1.y, p2.x, p2.y, p3.x, p3.y};

    float sx = 0.0f, sy = 0.0f, sz = 0.0f;
#pragma unroll
    for (int j = 0; j < KNBR; j++) {
        const int id = idx[j];
        if (id >= 0) {
            const float4 nv = d[id];
            sx += nv.x; sy += nv.y; sz += nv.z;
        }
    }
    const float inv = 1.0f / (float)p4.y;
    const float ex = di.x - sx * inv;
    const float ey = di.y - sy * inv;
    const float ez = di.z - sz * inv;
    return ex * ex + ey * ey + ez * ez;
}

// Block reduction -> scaled atomicAdd into g_acc; counts toward g_done.
__device__ __forceinline__ void block_add_count(float v, double scale) {
#pragma unroll
    for (int off = 16; off > 0; off >>= 1)
        v += __shfl_down_sync(0xFFFFFFFFu, v, off);

    __shared__ float warp_sums[TPB / 32];
    const int lane = threadIdx.x & 31;
    const int wid  = threadIdx.x >> 5;
    if (lane == 0) warp_sums[wid] = v;
    __syncthreads();

    if (wid == 0) {
        float s = (lane < (TPB >> 5)) ? warp_sums[lane] : 0.0f;
#pragma unroll
        for (int off = 4; off > 0; off >>= 1)
            s += __shfl_down_sync(0xFFFFFFFFu, s, off);
        if (lane == 0) {
            atomicAdd(&g_acc, (double)s * scale);
            __threadfence();
            atomicAdd(&g_done, 1u);
        }
    }
}

// ---------------------------------------------------------------------------
// K1: diff FINE (critical-path producer) + reset state.
// ---------------------------------------------------------------------------
__global__ void diff_fine_kernel(const float* __restrict__ fi,
                                 const float* __restrict__ fp,
                                 int nc, int nf) {
    __shared__ float s[3 * TPB];
    if (blockIdx.x == 0 && threadIdx.x == 0) { g_acc = 0.0; g_done = 0u; }
    diff_tile(fi, fp, nf, nc, blockIdx.x, s);
}

// ---------------------------------------------------------------------------
// K2: mixed — blocks [0, flb) compute loss_fine (the ~72us pole, scheduled
// first so it grabs SMs first); blocks [flb, ..) do diff_coarse (small DRAM
// job, hides under the pole). Independent halves. No reg cap (R15 lesson).
// ---------------------------------------------------------------------------
__global__ void mixed_kernel(const int* __restrict__ lif,
                             const float* __restrict__ ci,
                             const float* __restrict__ cp,
                             int nc, int nf, int flb, double sf) {
    const int b = blockIdx.x;
    if (b < flb) {
        const int i = b * TPB + threadIdx.x;
        float v = (i < nf) ? loss_vertex(lif, g_d + nc, i) : 0.0f;
        block_add_count(v, sf);
    } else {
        __shared__ float s[3 * TPB];
        diff_tile(ci, cp, nc, 0, b - flb, s);
    }
}

// ---------------------------------------------------------------------------
// K3: loss_coarse + last-block finalize (last launch -> finishing block here).
// ---------------------------------------------------------------------------
__global__ void loss_coarse_kernel(const int* __restrict__ lic, int nc,
                                   double sc, unsigned int total_blocks,
                                   float* __restrict__ out) {
    const int i = blockIdx.x * TPB + threadIdx.x;
    float v = (i < nc) ? loss_vertex(lic, g_d, i) : 0.0f;

#pragma unroll
    for (int off = 16; off > 0; off >>= 1)
        v += __shfl_down_sync(0xFFFFFFFFu, v, off);

    __shared__ float warp_sums[TPB / 32];
    __shared__ bool is_last;
    const int lane = threadIdx.x & 31;
    const int wid  = threadIdx.x >> 5;
    if (lane == 0) warp_sums[wid] = v;
    __syncthreads();

    if (wid == 0) {
        float s = (lane < (TPB >> 5)) ? warp_sums[lane] : 0.0f;
#pragma unroll
        for (int off = 4; off > 0; off >>= 1)
            s += __shfl_down_sync(0xFFFFFFFFu, s, off);
        if (lane == 0) {
            atomicAdd(&g_acc, (double)s * sc);
            __threadfence();
            unsigned int old = atomicAdd(&g_done, 1u);
            is_last = (old == total_blocks - 1u);
        }
    }
    __syncthreads();

    if (is_last && threadIdx.x == 0) {
        __threadfence();
        out[0] = (float)g_acc;
    }
}

extern "C" void kernel_launch(void* const* d_in, const int* in_sizes, int n_in,
                              void* d_out, int out_size) {
    const float* ci = (const float*)d_in[0];  // coarse_input  (N_C,3)
    const float* cp = (const float*)d_in[1];  // coarse_pred   (N_C,3)
    const float* fi = (const float*)d_in[2];  // fine_input    (N_F,3)
    const float* fp = (const float*)d_in[3];  // fine_pred     (N_F,3)
    const int* lic  = (const int*)d_in[4];    // lap_idx_coarse (N_C,10)
    const int* lif  = (const int*)d_in[5];    // lap_idx_fine   (N_F,10)

    const int nc = in_sizes[0] / 3;
    const int nf = in_sizes[2] / 3;

    const int cb  = (nc + TPB - 1) / TPB;   // coarse tiles / loss blocks
    const int fb  = (nf + TPB - 1) / TPB;   // fine tiles / loss blocks
    const unsigned int total = (unsigned int)(cb + fb);  // loss blocks overall

    diff_fine_kernel<<<fb, TPB>>>(fi, fp, nc, nf);
    mixed_kernel<<<fb + cb, TPB>>>(lif, ci, cp, nc, nf, fb, 0.5 / (double)nf);
    loss_coarse_kernel<<<cb, TPB>>>(lic, nc, 0.5 / (double)nc, total,
                                    (float*)d_out);
}